// round 10
// baseline (speedup 1.0000x reference)
#include <cuda_runtime.h>
#include <cuda_bf16.h>
#include <stdint.h>
#include <math.h>

// Problem shape (fixed by dataset)
static constexpr int Bb = 4;
static constexpr int Ss = 2048;
static constexpr int Ee = 1024;
static constexpr int Dd = 1024;

// ---------------- scratch (__device__ globals; allocation-free) ----------------
// Keep total ≈164 MB (R4/R5-proven level).
__device__ float g_q[(size_t)Bb * Ss * Dd];   // 32 MB
__device__ float g_k[(size_t)Bb * Ss * Dd];   // 32 MB
__device__ float g_v[(size_t)Bb * Ss * Dd];   // 32 MB
__device__ float g_p[(size_t)Bb * Ss * Ss];   // 67 MB
// canary slabs: 128x1024 bf16 hi/lo for x and wq (1 MB total)
__device__ __nv_bfloat16 g_cxh[128 * 1024], g_cxl[128 * 1024];
__device__ __nv_bfloat16 g_cwh[128 * 1024], g_cwl[128 * 1024];

// ---------------- mma helpers (canary path) ----------------
__device__ __forceinline__ uint32_t smem_u32(const void* p) {
    uint32_t a;
    asm("{ .reg .u64 t; cvta.to.shared.u64 t, %1; cvt.u32.u64 %0, t; }" : "=r"(a) : "l"(p));
    return a;
}
#define SW64(o) ((o) ^ (((o) >> 3) & 0x30))

__device__ __forceinline__ void ldsm4(uint32_t* r, uint32_t a) {
    asm volatile("ldmatrix.sync.aligned.m8n8.x4.shared.b16 {%0,%1,%2,%3}, [%4];"
        : "=r"(r[0]), "=r"(r[1]), "=r"(r[2]), "=r"(r[3]) : "r"(a));
}
__device__ __forceinline__ void ldsm4_trans(uint32_t* r, uint32_t a) {
    asm volatile("ldmatrix.sync.aligned.m8n8.x4.trans.shared.b16 {%0,%1,%2,%3}, [%4];"
        : "=r"(r[0]), "=r"(r[1]), "=r"(r[2]), "=r"(r[3]) : "r"(a));
}
__device__ __forceinline__ void mma_bf16(float* d, const uint32_t* a,
                                         uint32_t b0, uint32_t b1) {
    asm volatile("mma.sync.aligned.m16n8k16.row.col.f32.bf16.bf16.f32 "
        "{%0,%1,%2,%3}, {%4,%5,%6,%7}, {%8,%9}, {%0,%1,%2,%3};"
        : "+f"(d[0]), "+f"(d[1]), "+f"(d[2]), "+f"(d[3])
        : "r"(a[0]), "r"(a[1]), "r"(a[2]), "r"(a[3]), "r"(b0), "r"(b1));
}

static constexpr int SM_AH = 0;
static constexpr int SM_AL = 8192;
static constexpr int SM_BH = 16384;
static constexpr int SM_BL = 24576;
static constexpr int SM_TOTAL = 32768;

__device__ __forceinline__ void load_plane(char* smem, int off,
                                           const __nv_bfloat16* src, long ld,
                                           int tid) {
    #pragma unroll
    for (int j = 0; j < 2; j++) {
        int i = tid + j * 256;
        int row = i >> 2, c16 = i & 3;
        uint4 v = *(const uint4*)(src + (size_t)row * ld + c16 * 8);
        *(uint4*)(smem + off + SW64(row * 64 + c16 * 16)) = v;
    }
}

// fp32 -> (hi, lo) bf16 planes (canary feed)
__global__ void __launch_bounds__(256) convert_split(
    const float* __restrict__ src, __nv_bfloat16* __restrict__ hi,
    __nv_bfloat16* __restrict__ lo)
{
    size_t i = (size_t)blockIdx.x * 256 + threadIdx.x;
    float4 v = ((const float4*)src)[i];
    __nv_bfloat16 h0 = __float2bfloat16(v.x), h1 = __float2bfloat16(v.y);
    __nv_bfloat16 h2 = __float2bfloat16(v.z), h3 = __float2bfloat16(v.w);
    __nv_bfloat16 l0 = __float2bfloat16(v.x - __bfloat162float(h0));
    __nv_bfloat16 l1 = __float2bfloat16(v.y - __bfloat162float(h1));
    __nv_bfloat16 l2 = __float2bfloat16(v.z - __bfloat162float(h2));
    __nv_bfloat16 l3 = __float2bfloat16(v.w - __bfloat162float(h3));
    __nv_bfloat162 hA = __halves2bfloat162(h0, h1), hB = __halves2bfloat162(h2, h3);
    __nv_bfloat162 lA = __halves2bfloat162(l0, l1), lB = __halves2bfloat162(l2, l3);
    ((uint32_t*)hi)[i * 2]     = *(uint32_t*)&hA;
    ((uint32_t*)hi)[i * 2 + 1] = *(uint32_t*)&hB;
    ((uint32_t*)lo)[i * 2]     = *(uint32_t*)&lA;
    ((uint32_t*)lo)[i * 2 + 1] = *(uint32_t*)&lB;
}

// CANARY: one 128x128 split-bf16 mma tile into g_p[0:128][0:128] (later
// overwritten by scores_nt tile (0,0)). Exercises ldmatrix (+trans) and
// mma.sync on the real code path. 1 block only.
__global__ void __launch_bounds__(256) canary_mma()
{
    __shared__ __align__(128) char smem[SM_TOTAL];
    uint32_t sb = smem_u32(smem);
    int tid = threadIdx.x, lane = tid & 31, wid = tid >> 5;
    int wm = (wid & 3) * 32, wn = (wid >> 2) * 64;
    int r8 = lane & 7, sel = lane >> 3;

    int arb0 = (wm + (sel & 1) * 8 + r8) * 64 + (sel >> 1) * 16;
    int arb1 = arb0 + 16 * 64;
    int brb[4];
    #pragma unroll
    for (int j = 0; j < 4; j++)
        brb[j] = (wn + j * 16 + (sel & 1) * 8 + r8) * 64 + (sel >> 1) * 16;

    float acc[2][8][4] = {};

    for (int c = 0; c < Ee / 32; c++) {
        long co = (long)c * 32;
        load_plane(smem, SM_AH, g_cxh + co, Ee, tid);
        load_plane(smem, SM_AL, g_cxl + co, Ee, tid);
        load_plane(smem, SM_BH, g_cwh + co, Ee, tid);
        load_plane(smem, SM_BL, g_cwl + co, Ee, tid);
        __syncthreads();

        #pragma unroll
        for (int ks = 0; ks < 2; ks++) {
            int kb = ks * 32;
            uint32_t ah0[4], ah1[4], al0[4], al1[4];
            ldsm4(ah0, sb + SM_AH + SW64(arb0 + kb));
            ldsm4(ah1, sb + SM_AH + SW64(arb1 + kb));
            ldsm4(al0, sb + SM_AL + SW64(arb0 + kb));
            ldsm4(al1, sb + SM_AL + SW64(arb1 + kb));
            #pragma unroll
            for (int j = 0; j < 4; j++) {
                uint32_t bh[4], bl[4];
                ldsm4(bh, sb + SM_BH + SW64(brb[j] + kb));
                ldsm4(bl, sb + SM_BL + SW64(brb[j] + kb));
                mma_bf16(acc[0][2 * j],     ah0, bh[0], bh[2]);
                mma_bf16(acc[0][2 * j + 1], ah0, bh[1], bh[3]);
                mma_bf16(acc[1][2 * j],     ah1, bh[0], bh[2]);
                mma_bf16(acc[1][2 * j + 1], ah1, bh[1], bh[3]);
                mma_bf16(acc[0][2 * j],     ah0, bl[0], bl[2]);
                mma_bf16(acc[0][2 * j + 1], ah0, bl[1], bl[3]);
                mma_bf16(acc[1][2 * j],     ah1, bl[0], bl[2]);
                mma_bf16(acc[1][2 * j + 1], ah1, bl[1], bl[3]);
                mma_bf16(acc[0][2 * j],     al0, bh[0], bh[2]);
                mma_bf16(acc[0][2 * j + 1], al0, bh[1], bh[3]);
                mma_bf16(acc[1][2 * j],     al1, bh[0], bh[2]);
                mma_bf16(acc[1][2 * j + 1], al1, bh[1], bh[3]);
            }
        }
        __syncthreads();
    }

    // exercise ldmatrix.trans too (results folded in via 0-weight mma? no —
    // just issue it; asm volatile keeps it alive, results unused)
    {
        uint32_t t[4];
        ldsm4_trans(t, sb + SM_BH + SW64(brb[0]));
    }

    int rbase = wm + (lane >> 2);
    int cbase = wn + (lane & 3) * 2;
    #pragma unroll
    for (int i = 0; i < 2; i++)
        #pragma unroll
        for (int jn = 0; jn < 8; jn++)
            #pragma unroll
            for (int h = 0; h < 2; h++) {
                int row = rbase + i * 16 + h * 8;
                int col = cbase + jn * 8;
                *(float2*)(g_p + (size_t)row * Ss + col) =
                    make_float2(acc[i][jn][h * 2], acc[i][jn][h * 2 + 1]);
            }
}

// =================== R5-verbatim fp32 pipeline ===================
#define BM 128
#define BN 128
#define BK 16
#define TM 8
#define TN 8

#define COMPUTE_TILE(buf)                                                     \
    _Pragma("unroll")                                                         \
    for (int kk = 0; kk < BK; kk++) {                                         \
        float4 a0 = *(const float4*)&As[buf][kk][tr];                         \
        float4 a1 = *(const float4*)&As[buf][kk][tr + 4];                     \
        float4 b0 = *(const float4*)&Bs[buf][kk][tc];                         \
        float4 b1 = *(const float4*)&Bs[buf][kk][tc + 4];                     \
        float ra[8] = {a0.x, a0.y, a0.z, a0.w, a1.x, a1.y, a1.z, a1.w};       \
        float rb[8] = {b0.x, b0.y, b0.z, b0.w, b1.x, b1.y, b1.z, b1.w};       \
        _Pragma("unroll")                                                     \
        for (int i = 0; i < TM; i++)                                          \
            _Pragma("unroll")                                                 \
            for (int j = 0; j < TN; j++)                                      \
                acc[i][j] += ra[i] * rb[j];                                   \
    }

#define STORE_KT(dst, b_, v0, v1)                                             \
    dst[b_][lc4 + 0][lrow]      = v0.x;                                       \
    dst[b_][lc4 + 1][lrow]      = v0.y;                                       \
    dst[b_][lc4 + 2][lrow]      = v0.z;                                       \
    dst[b_][lc4 + 3][lrow]      = v0.w;                                       \
    dst[b_][lc4 + 0][lrow + 64] = v1.x;                                       \
    dst[b_][lc4 + 1][lrow + 64] = v1.y;                                       \
    dst[b_][lc4 + 2][lrow + 64] = v1.z;                                       \
    dst[b_][lc4 + 3][lrow + 64] = v1.w;

#define EPILOGUE(Cp, N_)                                                      \
    _Pragma("unroll")                                                         \
    for (int i = 0; i < TM; i++) {                                            \
        float* crow = Cp + (size_t)(by * BM + tr + i) * N_ + bx * BN + tc;    \
        *(float4*)(crow)     = make_float4(acc[i][0], acc[i][1], acc[i][2], acc[i][3]); \
        *(float4*)(crow + 4) = make_float4(acc[i][4], acc[i][5], acc[i][6], acc[i][7]); \
    }

__global__ void __launch_bounds__(256, 2) proj_all(
    const float* __restrict__ x,
    const float* __restrict__ wq, const float* __restrict__ wk,
    const float* __restrict__ wv)
{
    const int K = Ee, N = Dd;
    int bx = blockIdx.x, by = blockIdx.y, bz = blockIdx.z;
    const float* W = (bz == 0) ? wq : (bz == 1) ? wk : wv;
    float* C = (bz == 0) ? g_q : (bz == 1) ? g_k : g_v;

    __shared__ float As[2][BK][BM];
    __shared__ float Bs[2][BK][BN];

    int tid = threadIdx.x;
    int tr = (tid >> 4) * TM, tc = (tid & 15) * TN;
    int lrow = tid >> 2, lc4 = (tid & 3) * 4;

    const float* Ab = x + (size_t)(by * BM + lrow) * K + lc4;
    const float* Bt = W + (size_t)(bx * BN + lrow) * K + lc4;

    float4 pa0 = *(const float4*)(Ab);
    float4 pa1 = *(const float4*)(Ab + (size_t)64 * K);
    float4 pb0 = *(const float4*)(Bt);
    float4 pb1 = *(const float4*)(Bt + (size_t)64 * K);
    STORE_KT(As, 0, pa0, pa1)
    STORE_KT(Bs, 0, pb0, pb1)
    __syncthreads();

    float acc[TM][TN] = {};
    int buf = 0;
    const int niter = K / BK;
    for (int it = 0; it < niter; ++it) {
        if (it + 1 < niter) {
            int k0n = (it + 1) * BK;
            pa0 = *(const float4*)(Ab + k0n);
            pa1 = *(const float4*)(Ab + (size_t)64 * K + k0n);
            pb0 = *(const float4*)(Bt + k0n);
            pb1 = *(const float4*)(Bt + (size_t)64 * K + k0n);
        }
        COMPUTE_TILE(buf)
        if (it + 1 < niter) {
            int nb = buf ^ 1;
            STORE_KT(As, nb, pa0, pa1)
            STORE_KT(Bs, nb, pb0, pb1)
            __syncthreads();
            buf = nb;
        }
    }
    EPILOGUE(C, N)
}

__global__ void __launch_bounds__(256, 2) scores_nt()
{
    int bx = blockIdx.x, by = blockIdx.y, bz = blockIdx.z;
    if (bx > by) return;

    const int K = Dd, N = Ss;
    const float* A = g_q + (size_t)bz * Ss * Dd;
    const float* B = g_k + (size_t)bz * Ss * Dd;
    float*       C = g_p + (size_t)bz * Ss * Ss;

    __shared__ float As[2][BK][BM];
    __shared__ float Bs[2][BK][BN];

    int tid = threadIdx.x;
    int tr = (tid >> 4) * TM, tc = (tid & 15) * TN;
    int lrow = tid >> 2, lc4 = (tid & 3) * 4;

    const float* Ab = A + (size_t)(by * BM + lrow) * K + lc4;
    const float* Bt = B + (size_t)(bx * BN + lrow) * K + lc4;

    float4 pa0 = *(const float4*)(Ab);
    float4 pa1 = *(const float4*)(Ab + (size_t)64 * K);
    float4 pb0 = *(const float4*)(Bt);
    float4 pb1 = *(const float4*)(Bt + (size_t)64 * K);
    STORE_KT(As, 0, pa0, pa1)
    STORE_KT(Bs, 0, pb0, pb1)
    __syncthreads();

    float acc[TM][TN] = {};
    int buf = 0;
    const int niter = K / BK;
    for (int it = 0; it < niter; ++it) {
        if (it + 1 < niter) {
            int k0n = (it + 1) * BK;
            pa0 = *(const float4*)(Ab + k0n);
            pa1 = *(const float4*)(Ab + (size_t)64 * K + k0n);
            pb0 = *(const float4*)(Bt + k0n);
            pb1 = *(const float4*)(Bt + (size_t)64 * K + k0n);
        }
        COMPUTE_TILE(buf)
        if (it + 1 < niter) {
            int nb = buf ^ 1;
            STORE_KT(As, nb, pa0, pa1)
            STORE_KT(Bs, nb, pb0, pb1)
            __syncthreads();
            buf = nb;
        }
    }
    EPILOGUE(C, N)
}

__global__ void __launch_bounds__(256) softmax_causal()
{
    const int S = Ss;
    int row = blockIdx.x;
    int b = row >> 11, s = row & (S - 1);
    float* p = g_p + (size_t)b * S * S + (size_t)s * S;
    int L = s + 1;
    const float scale = 0.03125f;
    int tid = threadIdx.x;

    __shared__ float red[8];

    float m = -1e30f;
    for (int i = tid; i < L; i += 256) m = fmaxf(m, p[i]);
    #pragma unroll
    for (int o = 16; o; o >>= 1) m = fmaxf(m, __shfl_xor_sync(0xFFFFFFFFu, m, o));
    if ((tid & 31) == 0) red[tid >> 5] = m;
    __syncthreads();
    if (tid == 0) {
        float mm = red[0];
        #pragma unroll
        for (int i = 1; i < 8; i++) mm = fmaxf(mm, red[i]);
        red[0] = mm;
    }
    __syncthreads();
    m = red[0] * scale;
    __syncthreads();

    float sum = 0.f;
    for (int i = tid; i < L; i += 256) sum += __expf(p[i] * scale - m);
    #pragma unroll
    for (int o = 16; o; o >>= 1) sum += __shfl_xor_sync(0xFFFFFFFFu, sum, o);
    if ((tid & 31) == 0) red[tid >> 5] = sum;
    __syncthreads();
    if (tid == 0) {
        float ss = 0.f;
        #pragma unroll
        for (int i = 0; i < 8; i++) ss += red[i];
        red[0] = ss;
    }
    __syncthreads();
    float inv = 1.0f / red[0];

    for (int i = tid; i < S; i += 256)
        p[i] = (i < L) ? __expf(p[i] * scale - m) * inv : 0.0f;
}

__global__ void __launch_bounds__(256, 2) av_nn(float* __restrict__ out)
{
    int bx = blockIdx.x, by = blockIdx.y, bz = blockIdx.z;
    const int K = Ss, N = Dd;
    const float* A  = g_p + (size_t)bz * Ss * Ss;
    const float* Bm = g_v + (size_t)bz * Ss * Dd;
    float*       C  = out + (size_t)bz * Ss * Dd;

    int kmax = (by + 1) * BM;
    if (kmax > K) kmax = K;

    __shared__ float As[2][BK][BM];
    __shared__ float Bs[2][BK][BN];

    int tid = threadIdx.x;
    int tr = (tid >> 4) * TM, tc = (tid & 15) * TN;
    int lrow = tid >> 2, lc4 = (tid & 3) * 4;
    int brow = tid >> 5, bcc = (tid & 31) * 4;

    const float* Ab = A + (size_t)(by * BM + lrow) * K + lc4;
    const float* Bbp = Bm + bx * BN + bcc;

    float4 pa0 = *(const float4*)(Ab);
    float4 pa1 = *(const float4*)(Ab + (size_t)64 * K);
    float4 pb0 = *(const float4*)(Bbp + (size_t)brow * N);
    float4 pb1 = *(const float4*)(Bbp + (size_t)(brow + 8) * N);
    STORE_KT(As, 0, pa0, pa1)
    *(float4*)&Bs[0][brow][bcc]     = pb0;
    *(float4*)&Bs[0][brow + 8][bcc] = pb1;
    __syncthreads();

    float acc[TM][TN] = {};
    int buf = 0;
    const int niter = kmax / BK;
    for (int it = 0; it < niter; ++it) {
        if (it + 1 < niter) {
            int k0n = (it + 1) * BK;
            pa0 = *(const float4*)(Ab + k0n);
            pa1 = *(const float4*)(Ab + (size_t)64 * K + k0n);
            pb0 = *(const float4*)(Bbp + (size_t)(k0n + brow) * N);
            pb1 = *(const float4*)(Bbp + (size_t)(k0n + brow + 8) * N);
        }
        COMPUTE_TILE(buf)
        if (it + 1 < niter) {
            int nb = buf ^ 1;
            STORE_KT(As, nb, pa0, pa1)
            *(float4*)&Bs[nb][brow][bcc]     = pb0;
            *(float4*)&Bs[nb][brow + 8][bcc] = pb1;
            __syncthreads();
            buf = nb;
        }
    }
    EPILOGUE(C, N)
}

// ---------------- launch ----------------
extern "C" void kernel_launch(void* const* d_in, const int* in_sizes, int n_in,
                              void* d_out, int out_size)
{
    const float* x  = (const float*)d_in[0];
    const float* wq = (const float*)d_in[1];
    const float* wk = (const float*)d_in[2];
    const float* wv = (const float*)d_in[3];
    float* out = (float*)d_out;

    dim3 blk(256);

    // --- canary: convert 128-row slabs + 1-CTA mma tile (overwritten later) ---
    convert_split<<<(128 * 1024) / 4 / 256, blk>>>(x, g_cxh, g_cxl);
    convert_split<<<(128 * 1024) / 4 / 256, blk>>>(wq, g_cwh, g_cwl);
    canary_mma<<<1, blk>>>();

    // --- proven fp32 pipeline (R5) ---
    proj_all<<<dim3(Dd / BN, (Bb * Ss) / BM, 3), blk>>>(x, wq, wk, wv);
    scores_nt<<<dim3(Ss / BN, Ss / BM, Bb), blk>>>();
    softmax_causal<<<Bb * Ss, blk>>>();
    av_nn<<<dim3(Dd / BN, Ss / BM, Bb), blk>>>(out);
}